// round 1
// baseline (speedup 1.0000x reference)
#include <cuda_runtime.h>
#include <math.h>

static constexpr int BATCH   = 8192;
static constexpr int NPTS    = 2048;
static constexpr int THREADS = 256;

__global__ void __launch_bounds__(THREADS)
kabsch_kernel(const float* __restrict__ src,
              const float* __restrict__ corr,
              const float* __restrict__ wts,
              float* __restrict__ out)
{
    const int b   = blockIdx.x;
    const int tid = threadIdx.x;

    const size_t base3 = (size_t)b * 3 * NPTS;
    const float4* ax = (const float4*)(src  + base3);
    const float4* ay = (const float4*)(src  + base3 + NPTS);
    const float4* az = (const float4*)(src  + base3 + 2 * NPTS);
    const float4* bx = (const float4*)(corr + base3);
    const float4* by = (const float4*)(corr + base3 + NPTS);
    const float4* bz = (const float4*)(corr + base3 + 2 * NPTS);
    const float4* wp = (const float4*)(wts  + (size_t)b * NPTS);

    // 16 moments: [0]=Σw, [1..3]=Σw*a, [4..6]=Σw*b, [7+3d+e]=Σw*a_d*b_e
    float acc[16];
#pragma unroll
    for (int i = 0; i < 16; i++) acc[i] = 0.f;

#pragma unroll
    for (int it = 0; it < NPTS / (THREADS * 4); it++) {
        const int idx = it * THREADS + tid;
        const float4 vax = __ldg(ax + idx);
        const float4 vay = __ldg(ay + idx);
        const float4 vaz = __ldg(az + idx);
        const float4 vbx = __ldg(bx + idx);
        const float4 vby = __ldg(by + idx);
        const float4 vbz = __ldg(bz + idx);
        const float4 vw  = __ldg(wp + idx);

        const float wv[4]  = {vw.x,  vw.y,  vw.z,  vw.w};
        const float axv[4] = {vax.x, vax.y, vax.z, vax.w};
        const float ayv[4] = {vay.x, vay.y, vay.z, vay.w};
        const float azv[4] = {vaz.x, vaz.y, vaz.z, vaz.w};
        const float bxv[4] = {vbx.x, vbx.y, vbx.z, vbx.w};
        const float byv[4] = {vby.x, vby.y, vby.z, vby.w};
        const float bzv[4] = {vbz.x, vbz.y, vbz.z, vbz.w};

#pragma unroll
        for (int j = 0; j < 4; j++) {
            const float wi = wv[j];
            const float wax = wi * axv[j];
            const float way = wi * ayv[j];
            const float waz = wi * azv[j];
            acc[0] += wi;
            acc[1] += wax;
            acc[2] += way;
            acc[3] += waz;
            acc[4]  = fmaf(wi,  bxv[j], acc[4]);
            acc[5]  = fmaf(wi,  byv[j], acc[5]);
            acc[6]  = fmaf(wi,  bzv[j], acc[6]);
            acc[7]  = fmaf(wax, bxv[j], acc[7]);
            acc[8]  = fmaf(wax, byv[j], acc[8]);
            acc[9]  = fmaf(wax, bzv[j], acc[9]);
            acc[10] = fmaf(way, bxv[j], acc[10]);
            acc[11] = fmaf(way, byv[j], acc[11]);
            acc[12] = fmaf(way, bzv[j], acc[12]);
            acc[13] = fmaf(waz, bxv[j], acc[13]);
            acc[14] = fmaf(waz, byv[j], acc[14]);
            acc[15] = fmaf(waz, bzv[j], acc[15]);
        }
    }

    // ---- block reduction of 16 moments ----
    const int lane = tid & 31;
    const int warp = tid >> 5;
    __shared__ float red[8][16];

#pragma unroll
    for (int i = 0; i < 16; i++) {
#pragma unroll
        for (int off = 16; off; off >>= 1)
            acc[i] += __shfl_xor_sync(0xffffffffu, acc[i], off);
    }
    if (lane == 0) {
#pragma unroll
        for (int i = 0; i < 16; i++) red[warp][i] = acc[i];
    }
    __syncthreads();
    if (tid < 16) {
        float v = red[0][tid];
#pragma unroll
        for (int w = 1; w < 8; w++) v += red[w][tid];
        red[0][tid] = v;
    }
    __syncthreads();

    if (tid != 0) return;

    // ---- epilogue: centroids, covariance, Horn quaternion via 4x4 Jacobi ----
    float m[16];
#pragma unroll
    for (int i = 0; i < 16; i++) m[i] = red[0][i];

    const float Ssum = m[0] + 1e-5f;
    const float inv  = 1.f / Ssum;
    const float Wn   = m[0] * inv;          // Σ wn
    const float ca[3] = {m[1] * inv, m[2] * inv, m[3] * inv};
    const float cb[3] = {m[4] * inv, m[5] * inv, m[6] * inv};

    // cov[d][e] = Σ wn (a_d - ca_d)(b_e - cb_e)
    //           = Sab[d][e]/S - ca_d*cb_e*(2 - Wn)
    float cov[3][3];
    const float fac = 2.f - Wn;
#pragma unroll
    for (int d = 0; d < 3; d++)
#pragma unroll
        for (int e = 0; e < 3; e++)
            cov[d][e] = m[7 + 3 * d + e] * inv - ca[d] * cb[e] * fac;

    const float Sxx = cov[0][0], Sxy = cov[0][1], Sxz = cov[0][2];
    const float Syx = cov[1][0], Syy = cov[1][1], Syz = cov[1][2];
    const float Szx = cov[2][0], Szy = cov[2][1], Szz = cov[2][2];

    // Horn's 4x4 symmetric matrix (S_{de} = Σ wn a_d b_e, centered)
    float A[4][4];
    A[0][0] =  Sxx + Syy + Szz;
    A[0][1] =  Syz - Szy;
    A[0][2] =  Szx - Sxz;
    A[0][3] =  Sxy - Syx;
    A[1][1] =  Sxx - Syy - Szz;
    A[1][2] =  Sxy + Syx;
    A[1][3] =  Szx + Sxz;
    A[2][2] = -Sxx + Syy - Szz;
    A[2][3] =  Syz + Szy;
    A[3][3] = -Sxx - Syy + Szz;
    A[1][0] = A[0][1]; A[2][0] = A[0][2]; A[3][0] = A[0][3];
    A[2][1] = A[1][2]; A[3][1] = A[1][3]; A[3][2] = A[2][3];

    float V[4][4] = {{1,0,0,0},{0,1,0,0},{0,0,1,0},{0,0,0,1}};

    // cyclic Jacobi, 10 sweeps (far past fp32 convergence for 4x4)
    for (int sweep = 0; sweep < 10; sweep++) {
        for (int p = 0; p < 3; p++) {
            for (int q = p + 1; q < 4; q++) {
                const float apq = A[p][q];
                if (fabsf(apq) < 1e-20f) continue;
                const float theta = (A[q][q] - A[p][p]) / (2.f * apq);
                const float t = copysignf(1.f, theta) /
                                (fabsf(theta) + sqrtf(theta * theta + 1.f));
                const float c = rsqrtf(t * t + 1.f);
                const float s = t * c;
                // A = G^T A G with G[p][p]=c, G[q][q]=c, G[p][q]=s, G[q][p]=-s
#pragma unroll
                for (int k = 0; k < 4; k++) {           // A := A G
                    const float akp = A[k][p], akq = A[k][q];
                    A[k][p] = c * akp - s * akq;
                    A[k][q] = s * akp + c * akq;
                }
#pragma unroll
                for (int k = 0; k < 4; k++) {           // A := G^T A
                    const float apk = A[p][k], aqk = A[q][k];
                    A[p][k] = c * apk - s * aqk;
                    A[q][k] = s * apk + c * aqk;
                }
#pragma unroll
                for (int k = 0; k < 4; k++) {           // V := V G
                    const float vkp = V[k][p], vkq = V[k][q];
                    V[k][p] = c * vkp - s * vkq;
                    V[k][q] = s * vkp + c * vkq;
                }
            }
        }
    }

    // max-eigenvalue eigenvector = optimal quaternion
    int kbest = 0;
    float best = A[0][0];
#pragma unroll
    for (int i = 1; i < 4; i++)
        if (A[i][i] > best) { best = A[i][i]; kbest = i; }

    float q0 = V[0][kbest], qx = V[1][kbest], qy = V[2][kbest], qz = V[3][kbest];
    const float nrm = rsqrtf(q0 * q0 + qx * qx + qy * qy + qz * qz);
    q0 *= nrm; qx *= nrm; qy *= nrm; qz *= nrm;

    float R[3][3];
    R[0][0] = 1.f - 2.f * (qy * qy + qz * qz);
    R[0][1] = 2.f * (qx * qy - q0 * qz);
    R[0][2] = 2.f * (qx * qz + q0 * qy);
    R[1][0] = 2.f * (qx * qy + q0 * qz);
    R[1][1] = 1.f - 2.f * (qx * qx + qz * qz);
    R[1][2] = 2.f * (qy * qz - q0 * qx);
    R[2][0] = 2.f * (qx * qz - q0 * qy);
    R[2][1] = 2.f * (qy * qz + q0 * qx);
    R[2][2] = 1.f - 2.f * (qx * qx + qy * qy);

    float tr[3];
#pragma unroll
    for (int i = 0; i < 3; i++)
        tr[i] = cb[i] - (R[i][0] * ca[0] + R[i][1] * ca[1] + R[i][2] * ca[2]);

    // output: rot (B,3,3) flattened, then translation (B,3)
    float* ro = out + (size_t)b * 9;
#pragma unroll
    for (int i = 0; i < 3; i++)
#pragma unroll
        for (int j = 0; j < 3; j++)
            ro[i * 3 + j] = R[i][j];

    float* to = out + (size_t)BATCH * 9 + (size_t)b * 3;
    to[0] = tr[0]; to[1] = tr[1]; to[2] = tr[2];
}

extern "C" void kernel_launch(void* const* d_in, const int* in_sizes, int n_in,
                              void* d_out, int out_size)
{
    const float* src  = (const float*)d_in[0];
    const float* corr = (const float*)d_in[1];
    const float* wts  = (const float*)d_in[2];
    float* out = (float*)d_out;
    kabsch_kernel<<<BATCH, THREADS>>>(src, corr, wts, out);
}

// round 2
// speedup vs baseline: 1.1941x; 1.1941x over previous
#include <cuda_runtime.h>
#include <math.h>

static constexpr int BATCH   = 8192;
static constexpr int NPTS    = 2048;
static constexpr int THREADS = 256;               // 8 warps/CTA, 1 warp = 1 batch
static constexpr int WARPS_PER_CTA = THREADS / 32;
static constexpr int ITERS = NPTS / (32 * 4);     // 16 float4 iterations per lane

__global__ void __launch_bounds__(THREADS)
kabsch_kernel(const float* __restrict__ src,
              const float* __restrict__ corr,
              const float* __restrict__ wts,
              float* __restrict__ out)
{
    const int lane = threadIdx.x & 31;
    const int b    = blockIdx.x * WARPS_PER_CTA + (threadIdx.x >> 5);   // batch id

    const size_t base3 = (size_t)b * 3 * NPTS;
    const float4* ax = (const float4*)(src  + base3);
    const float4* ay = (const float4*)(src  + base3 + NPTS);
    const float4* az = (const float4*)(src  + base3 + 2 * NPTS);
    const float4* bx = (const float4*)(corr + base3);
    const float4* by = (const float4*)(corr + base3 + NPTS);
    const float4* bz = (const float4*)(corr + base3 + 2 * NPTS);
    const float4* wp = (const float4*)(wts  + (size_t)b * NPTS);

    // 16 moments: [0]=Σw, [1..3]=Σw*a, [4..6]=Σw*b, [7+3d+e]=Σw*a_d*b_e
    float acc[16];
#pragma unroll
    for (int i = 0; i < 16; i++) acc[i] = 0.f;

    // software-pipelined stream: prefetch iter j+1 while accumulating iter j
    float4 cw, cax, cay, caz, cbx, cby, cbz;
    {
        const int idx = lane;
        cw  = __ldg(wp + idx);
        cax = __ldg(ax + idx); cay = __ldg(ay + idx); caz = __ldg(az + idx);
        cbx = __ldg(bx + idx); cby = __ldg(by + idx); cbz = __ldg(bz + idx);
    }

#pragma unroll 2
    for (int it = 0; it < ITERS; it++) {
        float4 nw, nax, nay, naz, nbx, nby, nbz;
        if (it + 1 < ITERS) {
            const int idx = lane + 32 * (it + 1);
            nw  = __ldg(wp + idx);
            nax = __ldg(ax + idx); nay = __ldg(ay + idx); naz = __ldg(az + idx);
            nbx = __ldg(bx + idx); nby = __ldg(by + idx); nbz = __ldg(bz + idx);
        }

        const float wv[4]  = {cw.x,  cw.y,  cw.z,  cw.w};
        const float axv[4] = {cax.x, cax.y, cax.z, cax.w};
        const float ayv[4] = {cay.x, cay.y, cay.z, cay.w};
        const float azv[4] = {caz.x, caz.y, caz.z, caz.w};
        const float bxv[4] = {cbx.x, cbx.y, cbx.z, cbx.w};
        const float byv[4] = {cby.x, cby.y, cby.z, cby.w};
        const float bzv[4] = {cbz.x, cbz.y, cbz.z, cbz.w};

#pragma unroll
        for (int j = 0; j < 4; j++) {
            const float wi  = wv[j];
            const float wax = wi * axv[j];
            const float way = wi * ayv[j];
            const float waz = wi * azv[j];
            acc[0] += wi;
            acc[1] += wax;
            acc[2] += way;
            acc[3] += waz;
            acc[4]  = fmaf(wi,  bxv[j], acc[4]);
            acc[5]  = fmaf(wi,  byv[j], acc[5]);
            acc[6]  = fmaf(wi,  bzv[j], acc[6]);
            acc[7]  = fmaf(wax, bxv[j], acc[7]);
            acc[8]  = fmaf(wax, byv[j], acc[8]);
            acc[9]  = fmaf(wax, bzv[j], acc[9]);
            acc[10] = fmaf(way, bxv[j], acc[10]);
            acc[11] = fmaf(way, byv[j], acc[11]);
            acc[12] = fmaf(way, bzv[j], acc[12]);
            acc[13] = fmaf(waz, bxv[j], acc[13]);
            acc[14] = fmaf(waz, byv[j], acc[14]);
            acc[15] = fmaf(waz, bzv[j], acc[15]);
        }

        cw = nw; cax = nax; cay = nay; caz = naz;
        cbx = nbx; cby = nby; cbz = nbz;
    }

    // ---- warp reduction of 16 moments (no smem, no barriers) ----
#pragma unroll
    for (int i = 0; i < 16; i++) {
#pragma unroll
        for (int off = 16; off; off >>= 1)
            acc[i] += __shfl_xor_sync(0xffffffffu, acc[i], off);
    }

    if (lane != 0) return;

    // ---- epilogue: centroids, covariance, Horn quaternion via 4x4 Jacobi ----
    const float Ssum = acc[0] + 1e-5f;
    const float inv  = 1.f / Ssum;
    const float Wn   = acc[0] * inv;
    const float ca[3] = {acc[1] * inv, acc[2] * inv, acc[3] * inv};
    const float cb[3] = {acc[4] * inv, acc[5] * inv, acc[6] * inv};

    // cov[d][e] = Sab[d][e]/S - ca_d*cb_e*(2 - Wn)
    float cov[3][3];
    const float fac = 2.f - Wn;
#pragma unroll
    for (int d = 0; d < 3; d++)
#pragma unroll
        for (int e = 0; e < 3; e++)
            cov[d][e] = acc[7 + 3 * d + e] * inv - ca[d] * cb[e] * fac;

    const float Sxx = cov[0][0], Sxy = cov[0][1], Sxz = cov[0][2];
    const float Syx = cov[1][0], Syy = cov[1][1], Syz = cov[1][2];
    const float Szx = cov[2][0], Szy = cov[2][1], Szz = cov[2][2];

    float A[4][4];
    A[0][0] =  Sxx + Syy + Szz;
    A[0][1] =  Syz - Szy;
    A[0][2] =  Szx - Sxz;
    A[0][3] =  Sxy - Syx;
    A[1][1] =  Sxx - Syy - Szz;
    A[1][2] =  Sxy + Syx;
    A[1][3] =  Szx + Sxz;
    A[2][2] = -Sxx + Syy - Szz;
    A[2][3] =  Syz + Szy;
    A[3][3] = -Sxx - Syy + Szz;
    A[1][0] = A[0][1]; A[2][0] = A[0][2]; A[3][0] = A[0][3];
    A[2][1] = A[1][2]; A[3][1] = A[1][3]; A[3][2] = A[2][3];

    float V[4][4] = {{1,0,0,0},{0,1,0,0},{0,0,1,0},{0,0,0,1}};

    // Frobenius-scale for the convergence test
    float fro = 0.f;
#pragma unroll
    for (int i = 0; i < 4; i++)
#pragma unroll
        for (int j = 0; j < 4; j++) fro += A[i][j] * A[i][j];
    const float tol2 = 1e-14f * fro + 1e-30f;

    for (int sweep = 0; sweep < 8; sweep++) {
        float off2 = A[0][1]*A[0][1] + A[0][2]*A[0][2] + A[0][3]*A[0][3]
                   + A[1][2]*A[1][2] + A[1][3]*A[1][3] + A[2][3]*A[2][3];
        if (off2 < tol2) break;
        for (int p = 0; p < 3; p++) {
            for (int q = p + 1; q < 4; q++) {
                const float apq = A[p][q];
                if (fabsf(apq) < 1e-20f) continue;
                const float theta = (A[q][q] - A[p][p]) / (2.f * apq);
                const float t = copysignf(1.f, theta) /
                                (fabsf(theta) + sqrtf(theta * theta + 1.f));
                const float c = rsqrtf(t * t + 1.f);
                const float s = t * c;
#pragma unroll
                for (int k = 0; k < 4; k++) {           // A := A G
                    const float akp = A[k][p], akq = A[k][q];
                    A[k][p] = c * akp - s * akq;
                    A[k][q] = s * akp + c * akq;
                }
#pragma unroll
                for (int k = 0; k < 4; k++) {           // A := G^T A
                    const float apk = A[p][k], aqk = A[q][k];
                    A[p][k] = c * apk - s * aqk;
                    A[q][k] = s * apk + c * aqk;
                }
#pragma unroll
                for (int k = 0; k < 4; k++) {           // V := V G
                    const float vkp = V[k][p], vkq = V[k][q];
                    V[k][p] = c * vkp - s * vkq;
                    V[k][q] = s * vkp + c * vkq;
                }
            }
        }
    }

    int kbest = 0;
    float best = A[0][0];
#pragma unroll
    for (int i = 1; i < 4; i++)
        if (A[i][i] > best) { best = A[i][i]; kbest = i; }

    float q0 = V[0][kbest], qx = V[1][kbest], qy = V[2][kbest], qz = V[3][kbest];
    const float nrm = rsqrtf(q0 * q0 + qx * qx + qy * qy + qz * qz);
    q0 *= nrm; qx *= nrm; qy *= nrm; qz *= nrm;

    float R[3][3];
    R[0][0] = 1.f - 2.f * (qy * qy + qz * qz);
    R[0][1] = 2.f * (qx * qy - q0 * qz);
    R[0][2] = 2.f * (qx * qz + q0 * qy);
    R[1][0] = 2.f * (qx * qy + q0 * qz);
    R[1][1] = 1.f - 2.f * (qx * qx + qz * qz);
    R[1][2] = 2.f * (qy * qz - q0 * qx);
    R[2][0] = 2.f * (qx * qz - q0 * qy);
    R[2][1] = 2.f * (qy * qz + q0 * qx);
    R[2][2] = 1.f - 2.f * (qx * qx + qy * qy);

    float tr[3];
#pragma unroll
    for (int i = 0; i < 3; i++)
        tr[i] = cb[i] - (R[i][0] * ca[0] + R[i][1] * ca[1] + R[i][2] * ca[2]);

    float* ro = out + (size_t)b * 9;
#pragma unroll
    for (int i = 0; i < 3; i++)
#pragma unroll
        for (int j = 0; j < 3; j++)
            ro[i * 3 + j] = R[i][j];

    float* to = out + (size_t)BATCH * 9 + (size_t)b * 3;
    to[0] = tr[0]; to[1] = tr[1]; to[2] = tr[2];
}

extern "C" void kernel_launch(void* const* d_in, const int* in_sizes, int n_in,
                              void* d_out, int out_size)
{
    const float* src  = (const float*)d_in[0];
    const float* corr = (const float*)d_in[1];
    const float* wts  = (const float*)d_in[2];
    float* out = (float*)d_out;
    kabsch_kernel<<<BATCH / WARPS_PER_CTA, THREADS>>>(src, corr, wts, out);
}

// round 3
// speedup vs baseline: 1.4141x; 1.1842x over previous
#include <cuda_runtime.h>
#include <math.h>

static constexpr int BATCH   = 8192;
static constexpr int NPTS    = 2048;
static constexpr int THREADS = 256;               // 8 warps/CTA, 1 warp = 1 batch
static constexpr int WARPS_PER_CTA = THREADS / 32;
static constexpr int ITERS = NPTS / (32 * 4);     // 16 float4 iterations per lane

// scratch: 16 moments per batch, SoA layout [moment][batch] for coalesced phase-2 reads
__device__ float g_moments[16 * BATCH];

// ---------------------------------------------------------------------------
// Phase 1: streaming moment accumulation (pure bandwidth kernel)
// ---------------------------------------------------------------------------
__global__ void __launch_bounds__(THREADS)
moments_kernel(const float* __restrict__ src,
               const float* __restrict__ corr,
               const float* __restrict__ wts)
{
    const int lane = threadIdx.x & 31;
    const int b    = blockIdx.x * WARPS_PER_CTA + (threadIdx.x >> 5);

    const size_t base3 = (size_t)b * 3 * NPTS;
    const float4* ax = (const float4*)(src  + base3);
    const float4* ay = (const float4*)(src  + base3 + NPTS);
    const float4* az = (const float4*)(src  + base3 + 2 * NPTS);
    const float4* bx = (const float4*)(corr + base3);
    const float4* by = (const float4*)(corr + base3 + NPTS);
    const float4* bz = (const float4*)(corr + base3 + 2 * NPTS);
    const float4* wp = (const float4*)(wts  + (size_t)b * NPTS);

    float acc[16];
#pragma unroll
    for (int i = 0; i < 16; i++) acc[i] = 0.f;

    // software pipeline: prefetch iter j+1 while accumulating iter j
    float4 cw, cax, cay, caz, cbx, cby, cbz;
    {
        cw  = __ldg(wp + lane);
        cax = __ldg(ax + lane); cay = __ldg(ay + lane); caz = __ldg(az + lane);
        cbx = __ldg(bx + lane); cby = __ldg(by + lane); cbz = __ldg(bz + lane);
    }

#pragma unroll 2
    for (int it = 0; it < ITERS; it++) {
        float4 nw, nax, nay, naz, nbx, nby, nbz;
        if (it + 1 < ITERS) {
            const int idx = lane + 32 * (it + 1);
            nw  = __ldg(wp + idx);
            nax = __ldg(ax + idx); nay = __ldg(ay + idx); naz = __ldg(az + idx);
            nbx = __ldg(bx + idx); nby = __ldg(by + idx); nbz = __ldg(bz + idx);
        }

        const float wv[4]  = {cw.x,  cw.y,  cw.z,  cw.w};
        const float axv[4] = {cax.x, cax.y, cax.z, cax.w};
        const float ayv[4] = {cay.x, cay.y, cay.z, cay.w};
        const float azv[4] = {caz.x, caz.y, caz.z, caz.w};
        const float bxv[4] = {cbx.x, cbx.y, cbx.z, cbx.w};
        const float byv[4] = {cby.x, cby.y, cby.z, cby.w};
        const float bzv[4] = {cbz.x, cbz.y, cbz.z, cbz.w};

#pragma unroll
        for (int j = 0; j < 4; j++) {
            const float wi  = wv[j];
            const float wax = wi * axv[j];
            const float way = wi * ayv[j];
            const float waz = wi * azv[j];
            acc[0] += wi;
            acc[1] += wax;
            acc[2] += way;
            acc[3] += waz;
            acc[4]  = fmaf(wi,  bxv[j], acc[4]);
            acc[5]  = fmaf(wi,  byv[j], acc[5]);
            acc[6]  = fmaf(wi,  bzv[j], acc[6]);
            acc[7]  = fmaf(wax, bxv[j], acc[7]);
            acc[8]  = fmaf(wax, byv[j], acc[8]);
            acc[9]  = fmaf(wax, bzv[j], acc[9]);
            acc[10] = fmaf(way, bxv[j], acc[10]);
            acc[11] = fmaf(way, byv[j], acc[11]);
            acc[12] = fmaf(way, bzv[j], acc[12]);
            acc[13] = fmaf(waz, bxv[j], acc[13]);
            acc[14] = fmaf(waz, byv[j], acc[14]);
            acc[15] = fmaf(waz, bzv[j], acc[15]);
        }

        cw = nw; cax = nax; cay = nay; caz = naz;
        cbx = nbx; cby = nby; cbz = nbz;
    }

    // warp reduction (no smem, no barriers)
#pragma unroll
    for (int i = 0; i < 16; i++) {
#pragma unroll
        for (int off = 16; off; off >>= 1)
            acc[i] += __shfl_xor_sync(0xffffffffu, acc[i], off);
    }

    if (lane == 0) {
#pragma unroll
        for (int i = 0; i < 16; i++)
            g_moments[i * BATCH + b] = acc[i];
    }
}

// ---------------------------------------------------------------------------
// Phase 2: one thread per batch — Horn quaternion via 4x4 Jacobi, all parallel
// ---------------------------------------------------------------------------
__global__ void __launch_bounds__(256)
epilogue_kernel(float* __restrict__ out)
{
    const int b = blockIdx.x * blockDim.x + threadIdx.x;
    if (b >= BATCH) return;

    float m[16];
#pragma unroll
    for (int i = 0; i < 16; i++) m[i] = g_moments[i * BATCH + b];   // coalesced

    const float Ssum = m[0] + 1e-5f;
    const float inv  = 1.f / Ssum;
    const float Wn   = m[0] * inv;
    const float ca[3] = {m[1] * inv, m[2] * inv, m[3] * inv};
    const float cb[3] = {m[4] * inv, m[5] * inv, m[6] * inv};

    // cov[d][e] = Sab[d][e]/S - ca_d*cb_e*(2 - Wn)
    float cov[3][3];
    const float fac = 2.f - Wn;
#pragma unroll
    for (int d = 0; d < 3; d++)
#pragma unroll
        for (int e = 0; e < 3; e++)
            cov[d][e] = m[7 + 3 * d + e] * inv - ca[d] * cb[e] * fac;

    const float Sxx = cov[0][0], Sxy = cov[0][1], Sxz = cov[0][2];
    const float Syx = cov[1][0], Syy = cov[1][1], Syz = cov[1][2];
    const float Szx = cov[2][0], Szy = cov[2][1], Szz = cov[2][2];

    float A[4][4];
    A[0][0] =  Sxx + Syy + Szz;
    A[0][1] =  Syz - Szy;
    A[0][2] =  Szx - Sxz;
    A[0][3] =  Sxy - Syx;
    A[1][1] =  Sxx - Syy - Szz;
    A[1][2] =  Sxy + Syx;
    A[1][3] =  Szx + Sxz;
    A[2][2] = -Sxx + Syy - Szz;
    A[2][3] =  Syz + Szy;
    A[3][3] = -Sxx - Syy + Szz;
    A[1][0] = A[0][1]; A[2][0] = A[0][2]; A[3][0] = A[0][3];
    A[2][1] = A[1][2]; A[3][1] = A[1][3]; A[3][2] = A[2][3];

    float V[4][4] = {{1,0,0,0},{0,1,0,0},{0,0,1,0},{0,0,0,1}};

    float fro = 0.f;
#pragma unroll
    for (int i = 0; i < 4; i++)
#pragma unroll
        for (int j = 0; j < 4; j++) fro += A[i][j] * A[i][j];
    const float tol2 = 1e-14f * fro + 1e-30f;

    for (int sweep = 0; sweep < 8; sweep++) {
        float off2 = A[0][1]*A[0][1] + A[0][2]*A[0][2] + A[0][3]*A[0][3]
                   + A[1][2]*A[1][2] + A[1][3]*A[1][3] + A[2][3]*A[2][3];
        if (off2 < tol2) break;
        for (int p = 0; p < 3; p++) {
            for (int q = p + 1; q < 4; q++) {
                const float apq = A[p][q];
                if (fabsf(apq) < 1e-20f) continue;
                const float theta = (A[q][q] - A[p][p]) / (2.f * apq);
                const float t = copysignf(1.f, theta) /
                                (fabsf(theta) + sqrtf(theta * theta + 1.f));
                const float c = rsqrtf(t * t + 1.f);
                const float s = t * c;
#pragma unroll
                for (int k = 0; k < 4; k++) {           // A := A G
                    const float akp = A[k][p], akq = A[k][q];
                    A[k][p] = c * akp - s * akq;
                    A[k][q] = s * akp + c * akq;
                }
#pragma unroll
                for (int k = 0; k < 4; k++) {           // A := G^T A
                    const float apk = A[p][k], aqk = A[q][k];
                    A[p][k] = c * apk - s * aqk;
                    A[q][k] = s * apk + c * aqk;
                }
#pragma unroll
                for (int k = 0; k < 4; k++) {           // V := V G
                    const float vkp = V[k][p], vkq = V[k][q];
                    V[k][p] = c * vkp - s * vkq;
                    V[k][q] = s * vkp + c * vkq;
                }
            }
        }
    }

    int kbest = 0;
    float best = A[0][0];
#pragma unroll
    for (int i = 1; i < 4; i++)
        if (A[i][i] > best) { best = A[i][i]; kbest = i; }

    float q0 = V[0][kbest], qx = V[1][kbest], qy = V[2][kbest], qz = V[3][kbest];
    const float nrm = rsqrtf(q0 * q0 + qx * qx + qy * qy + qz * qz);
    q0 *= nrm; qx *= nrm; qy *= nrm; qz *= nrm;

    float R[3][3];
    R[0][0] = 1.f - 2.f * (qy * qy + qz * qz);
    R[0][1] = 2.f * (qx * qy - q0 * qz);
    R[0][2] = 2.f * (qx * qz + q0 * qy);
    R[1][0] = 2.f * (qx * qy + q0 * qz);
    R[1][1] = 1.f - 2.f * (qx * qx + qz * qz);
    R[1][2] = 2.f * (qy * qz - q0 * qx);
    R[2][0] = 2.f * (qx * qz - q0 * qy);
    R[2][1] = 2.f * (qy * qz + q0 * qx);
    R[2][2] = 1.f - 2.f * (qx * qx + qy * qy);

    float tr[3];
#pragma unroll
    for (int i = 0; i < 3; i++)
        tr[i] = cb[i] - (R[i][0] * ca[0] + R[i][1] * ca[1] + R[i][2] * ca[2]);

    float* ro = out + (size_t)b * 9;
#pragma unroll
    for (int i = 0; i < 3; i++)
#pragma unroll
        for (int j = 0; j < 3; j++)
            ro[i * 3 + j] = R[i][j];

    float* to = out + (size_t)BATCH * 9 + (size_t)b * 3;
    to[0] = tr[0]; to[1] = tr[1]; to[2] = tr[2];
}

extern "C" void kernel_launch(void* const* d_in, const int* in_sizes, int n_in,
                              void* d_out, int out_size)
{
    const float* src  = (const float*)d_in[0];
    const float* corr = (const float*)d_in[1];
    const float* wts  = (const float*)d_in[2];
    float* out = (float*)d_out;

    moments_kernel<<<BATCH / WARPS_PER_CTA, THREADS>>>(src, corr, wts);
    epilogue_kernel<<<BATCH / 256, 256>>>(out);
}

// round 4
// speedup vs baseline: 1.4269x; 1.0091x over previous
#include <cuda_runtime.h>
#include <math.h>

static constexpr int BATCH   = 8192;
static constexpr int NPTS    = 2048;
static constexpr int THREADS = 256;               // 8 warps/CTA, 1 warp = 1 batch
static constexpr int WARPS_PER_CTA = THREADS / 32;
static constexpr int ITERS = NPTS / (32 * 4);     // 16 float4 iterations per lane

// scratch: 16 moments per batch, SoA layout [moment][batch] for coalesced phase-2 reads
__device__ float g_moments[16 * BATCH];

// ---------------------------------------------------------------------------
// Phase 1: streaming moment accumulation (pure bandwidth kernel) — UNCHANGED
// ---------------------------------------------------------------------------
__global__ void __launch_bounds__(THREADS)
moments_kernel(const float* __restrict__ src,
               const float* __restrict__ corr,
               const float* __restrict__ wts)
{
    const int lane = threadIdx.x & 31;
    const int b    = blockIdx.x * WARPS_PER_CTA + (threadIdx.x >> 5);

    const size_t base3 = (size_t)b * 3 * NPTS;
    const float4* ax = (const float4*)(src  + base3);
    const float4* ay = (const float4*)(src  + base3 + NPTS);
    const float4* az = (const float4*)(src  + base3 + 2 * NPTS);
    const float4* bx = (const float4*)(corr + base3);
    const float4* by = (const float4*)(corr + base3 + NPTS);
    const float4* bz = (const float4*)(corr + base3 + 2 * NPTS);
    const float4* wp = (const float4*)(wts  + (size_t)b * NPTS);

    float acc[16];
#pragma unroll
    for (int i = 0; i < 16; i++) acc[i] = 0.f;

    float4 cw, cax, cay, caz, cbx, cby, cbz;
    {
        cw  = __ldg(wp + lane);
        cax = __ldg(ax + lane); cay = __ldg(ay + lane); caz = __ldg(az + lane);
        cbx = __ldg(bx + lane); cby = __ldg(by + lane); cbz = __ldg(bz + lane);
    }

#pragma unroll 2
    for (int it = 0; it < ITERS; it++) {
        float4 nw, nax, nay, naz, nbx, nby, nbz;
        if (it + 1 < ITERS) {
            const int idx = lane + 32 * (it + 1);
            nw  = __ldg(wp + idx);
            nax = __ldg(ax + idx); nay = __ldg(ay + idx); naz = __ldg(az + idx);
            nbx = __ldg(bx + idx); nby = __ldg(by + idx); nbz = __ldg(bz + idx);
        }

        const float wv[4]  = {cw.x,  cw.y,  cw.z,  cw.w};
        const float axv[4] = {cax.x, cax.y, cax.z, cax.w};
        const float ayv[4] = {cay.x, cay.y, cay.z, cay.w};
        const float azv[4] = {caz.x, caz.y, caz.z, caz.w};
        const float bxv[4] = {cbx.x, cbx.y, cbx.z, cbx.w};
        const float byv[4] = {cby.x, cby.y, cby.z, cby.w};
        const float bzv[4] = {cbz.x, cbz.y, cbz.z, cbz.w};

#pragma unroll
        for (int j = 0; j < 4; j++) {
            const float wi  = wv[j];
            const float wax = wi * axv[j];
            const float way = wi * ayv[j];
            const float waz = wi * azv[j];
            acc[0] += wi;
            acc[1] += wax;
            acc[2] += way;
            acc[3] += waz;
            acc[4]  = fmaf(wi,  bxv[j], acc[4]);
            acc[5]  = fmaf(wi,  byv[j], acc[5]);
            acc[6]  = fmaf(wi,  bzv[j], acc[6]);
            acc[7]  = fmaf(wax, bxv[j], acc[7]);
            acc[8]  = fmaf(wax, byv[j], acc[8]);
            acc[9]  = fmaf(wax, bzv[j], acc[9]);
            acc[10] = fmaf(way, bxv[j], acc[10]);
            acc[11] = fmaf(way, byv[j], acc[11]);
            acc[12] = fmaf(way, bzv[j], acc[12]);
            acc[13] = fmaf(waz, bxv[j], acc[13]);
            acc[14] = fmaf(waz, byv[j], acc[14]);
            acc[15] = fmaf(waz, bzv[j], acc[15]);
        }

        cw = nw; cax = nax; cay = nay; caz = naz;
        cbx = nbx; cby = nby; cbz = nbz;
    }

#pragma unroll
    for (int i = 0; i < 16; i++) {
#pragma unroll
        for (int off = 16; off; off >>= 1)
            acc[i] += __shfl_xor_sync(0xffffffffu, acc[i], off);
    }

    if (lane == 0) {
#pragma unroll
        for (int i = 0; i < 16; i++)
            g_moments[i * BATCH + b] = acc[i];
    }
}

// ---------------------------------------------------------------------------
// Branchless Jacobi rotation on the (p,q) plane of the 4x4 symmetric A,
// accumulating eigenvectors in V. Identity rotation when A[p][q] == 0.
// ---------------------------------------------------------------------------
__device__ __forceinline__ void jrot(float A[4][4], float V[4][4], int p, int q)
{
    const float apq = A[p][q];
    const float h   = 0.5f * (A[q][q] - A[p][p]);
    // t = tan(theta) of the smaller rotation angle; algebraically equal to
    // sign(h/apq) / (|h/apq| + sqrt((h/apq)^2 + 1)), but safe at apq == 0.
    const float t = apq * copysignf(1.f, h) /
                    (fabsf(h) + sqrtf(h * h + apq * apq) + 1e-30f);
    const float c = rsqrtf(t * t + 1.f);
    const float s = t * c;
#pragma unroll
    for (int k = 0; k < 4; k++) {           // A := A G
        const float akp = A[k][p], akq = A[k][q];
        A[k][p] = c * akp - s * akq;
        A[k][q] = s * akp + c * akq;
    }
#pragma unroll
    for (int k = 0; k < 4; k++) {           // A := G^T A
        const float apk = A[p][k], aqk = A[q][k];
        A[p][k] = c * apk - s * aqk;
        A[q][k] = s * apk + c * aqk;
    }
#pragma unroll
    for (int k = 0; k < 4; k++) {           // V := V G
        const float vkp = V[k][p], vkq = V[k][q];
        V[k][p] = c * vkp - s * vkq;
        V[k][q] = s * vkp + c * vkq;
    }
}

// ---------------------------------------------------------------------------
// Phase 2: one thread per batch — Horn quaternion via branchless 4x4 Jacobi
// ---------------------------------------------------------------------------
static constexpr int EPI_THREADS = 64;

__global__ void __launch_bounds__(EPI_THREADS)
epilogue_kernel(float* __restrict__ out)
{
    const int b = blockIdx.x * EPI_THREADS + threadIdx.x;

    float m[16];
#pragma unroll
    for (int i = 0; i < 16; i++) m[i] = g_moments[i * BATCH + b];   // coalesced

    const float Ssum = m[0] + 1e-5f;
    const float inv  = 1.f / Ssum;
    const float Wn   = m[0] * inv;
    const float ca[3] = {m[1] * inv, m[2] * inv, m[3] * inv};
    const float cb[3] = {m[4] * inv, m[5] * inv, m[6] * inv};

    // cov[d][e] = Sab[d][e]/S - ca_d*cb_e*(2 - Wn)
    float cov[3][3];
    const float fac = 2.f - Wn;
#pragma unroll
    for (int d = 0; d < 3; d++)
#pragma unroll
        for (int e = 0; e < 3; e++)
            cov[d][e] = m[7 + 3 * d + e] * inv - ca[d] * cb[e] * fac;

    const float Sxx = cov[0][0], Sxy = cov[0][1], Sxz = cov[0][2];
    const float Syx = cov[1][0], Syy = cov[1][1], Syz = cov[1][2];
    const float Szx = cov[2][0], Szy = cov[2][1], Szz = cov[2][2];

    float A[4][4];
    A[0][0] =  Sxx + Syy + Szz;
    A[0][1] =  Syz - Szy;
    A[0][2] =  Szx - Sxz;
    A[0][3] =  Sxy - Syx;
    A[1][1] =  Sxx - Syy - Szz;
    A[1][2] =  Sxy + Syx;
    A[1][3] =  Szx + Sxz;
    A[2][2] = -Sxx + Syy - Szz;
    A[2][3] =  Syz + Szy;
    A[3][3] = -Sxx - Syy + Szz;
    A[1][0] = A[0][1]; A[2][0] = A[0][2]; A[3][0] = A[0][3];
    A[2][1] = A[1][2]; A[3][1] = A[1][3]; A[3][2] = A[2][3];

    float V[4][4] = {{1,0,0,0},{0,1,0,0},{0,0,1,0},{0,0,0,1}};

    // fixed 5 cyclic sweeps, fully unrolled, branchless — no divergence
#pragma unroll
    for (int sweep = 0; sweep < 5; sweep++) {
        jrot(A, V, 0, 1);
        jrot(A, V, 0, 2);
        jrot(A, V, 0, 3);
        jrot(A, V, 1, 2);
        jrot(A, V, 1, 3);
        jrot(A, V, 2, 3);
    }

    // select eigenvector of the max eigenvalue (branchless)
    float best = A[0][0];
    int kbest = 0;
#pragma unroll
    for (int i = 1; i < 4; i++) {
        const bool gt = A[i][i] > best;
        best  = gt ? A[i][i] : best;
        kbest = gt ? i : kbest;
    }

    float q0 = V[0][kbest], qx = V[1][kbest], qy = V[2][kbest], qz = V[3][kbest];
    const float nrm = rsqrtf(q0 * q0 + qx * qx + qy * qy + qz * qz);
    q0 *= nrm; qx *= nrm; qy *= nrm; qz *= nrm;

    float R[3][3];
    R[0][0] = 1.f - 2.f * (qy * qy + qz * qz);
    R[0][1] = 2.f * (qx * qy - q0 * qz);
    R[0][2] = 2.f * (qx * qz + q0 * qy);
    R[1][0] = 2.f * (qx * qy + q0 * qz);
    R[1][1] = 1.f - 2.f * (qx * qx + qz * qz);
    R[1][2] = 2.f * (qy * qz - q0 * qx);
    R[2][0] = 2.f * (qx * qz - q0 * qy);
    R[2][1] = 2.f * (qy * qz + q0 * qx);
    R[2][2] = 1.f - 2.f * (qx * qx + qy * qy);

    float tr[3];
#pragma unroll
    for (int i = 0; i < 3; i++)
        tr[i] = cb[i] - (R[i][0] * ca[0] + R[i][1] * ca[1] + R[i][2] * ca[2]);

    float* ro = out + (size_t)b * 9;
#pragma unroll
    for (int i = 0; i < 3; i++)
#pragma unroll
        for (int j = 0; j < 3; j++)
            ro[i * 3 + j] = R[i][j];

    float* to = out + (size_t)BATCH * 9 + (size_t)b * 3;
    to[0] = tr[0]; to[1] = tr[1]; to[2] = tr[2];
}

extern "C" void kernel_launch(void* const* d_in, const int* in_sizes, int n_in,
                              void* d_out, int out_size)
{
    const float* src  = (const float*)d_in[0];
    const float* corr = (const float*)d_in[1];
    const float* wts  = (const float*)d_in[2];
    float* out = (float*)d_out;

    moments_kernel<<<BATCH / WARPS_PER_CTA, THREADS>>>(src, corr, wts);
    epilogue_kernel<<<BATCH / EPI_THREADS, EPI_THREADS>>>(out);
}